// round 12
// baseline (speedup 1.0000x reference)
#include <cuda_runtime.h>
#include <cuda_fp16.h>
#include <stdint.h>

#define N_NODES 100000
#define N_EDGES 1600000
#define CAP 64                   // padded adjacency capacity (max degree << 64 here)
#define GEMM1_BLKS 3125          // 32 rows per block
#define FB_BLKS 1563             // fused agg1+gemm2: 64 nodes per block

typedef unsigned long long u64;

// ---------------- scratch (zero-initialized at load; agg2 re-zeros g_deg) ----------------
__device__ int    g_deg[N_NODES];            // edge count (self-loop NOT included)
__device__ float  g_dinv[N_NODES];
__device__ u64    g_dinvp[N_NODES];          // packed {dinv, dinv} pairs for FMA2
__device__ int    g_adj[N_NODES * CAP];      // padded adjacency
__device__ u64    g_mask[N_NODES];           // dropout keep-mask, bit k = element node*64+k
__device__ float  g_hs1[N_NODES * 64];       // x@W1 (UNSCALED), fp32
__device__ float  g_hs2[N_NODES * 32];       // (h1@W2) * dinv[row], fp32

// ---------------- packed fp32x2 math (Blackwell f32x2 pipes) ----------------
#define FMA2(d, a, b) \
  asm("fma.rn.f32x2 %0, %1, %2, %3;" : "=l"(d) : "l"(a), "l"(b), "l"(d))
#define ADD2(d, a, b) \
  asm("add.rn.f32x2 %0, %1, %2;" : "=l"(d) : "l"(a), "l"(b))
#define PACK2(d, f) \
  asm("mov.b64 %0, {%1, %1};" : "=l"(d) : "f"(f))
#define UNPACK2(lo, hi, d) \
  asm("mov.b64 {%0, %1}, %2;" : "=f"(lo), "=f"(hi) : "l"(d))

// ---------------- per-block edge-dtype probe ----------------
__device__ __forceinline__ int probe_is64(const int* ei32, int tid, int* s_flag) {
  if (tid < 32) {
    int bad = (ei32[2 * tid + 1] != 0);
    unsigned m = __ballot_sync(0xffffffffu, bad);
    if (tid == 0) *s_flag = (m == 0);
  }
  __syncthreads();
  return *s_flag;
}

// ---------------- JAX threefry-2x32 (partitionable mode) ----------------
__device__ __forceinline__ unsigned tf_bits(unsigned i) {
  const unsigned ks0 = 0u;
  const unsigned ks1 = 42u;
  const unsigned ks2 = 0x1BD11BDAu ^ 0u ^ 42u;
  unsigned x0 = 0u + ks0;
  unsigned x1 = i  + ks1;
#define TF_R4(a,b,c,d) \
  x0 += x1; x1 = __funnelshift_l(x1, x1, (a)) ^ x0; \
  x0 += x1; x1 = __funnelshift_l(x1, x1, (b)) ^ x0; \
  x0 += x1; x1 = __funnelshift_l(x1, x1, (c)) ^ x0; \
  x0 += x1; x1 = __funnelshift_l(x1, x1, (d)) ^ x0;
  TF_R4(13,15,26, 6)  x0 += ks1; x1 += ks2 + 1u;
  TF_R4(17,29,16,24)  x0 += ks2; x1 += ks0 + 2u;
  TF_R4(13,15,26, 6)  x0 += ks0; x1 += ks1 + 3u;
  TF_R4(17,29,16,24)  x0 += ks1; x1 += ks2 + 4u;
  TF_R4(13,15,26, 6)  x0 += ks2; x1 += ks0 + 5u;
#undef TF_R4
  return x0 ^ x1;
}
#define TF_KEEP_THRESH 0xCCCCCE00u
#define INV_KEEP 1.25f

// ---------------- CSR build + dropout-mask generation ----------------
__global__ void k_degfill(const void* __restrict__ ei) {
  __shared__ int s_flag;
  int tid = threadIdx.x;
  int is64 = probe_is64((const int*)ei, tid, &s_flag);
  int t = blockIdx.x * 256 + tid;          // 0 .. 799999
  int e = t * 2;
  int s0, s1, d0, d1;
  if (is64) {
    longlong2 sv = *(const longlong2*)((const long long*)ei + e);
    longlong2 dv = *(const longlong2*)((const long long*)ei + N_EDGES + e);
    s0 = (int)sv.x; s1 = (int)sv.y; d0 = (int)dv.x; d1 = (int)dv.y;
  } else {
    int2 sv = *(const int2*)((const int*)ei + e);
    int2 dv = *(const int2*)((const int*)ei + N_EDGES + e);
    s0 = sv.x; s1 = sv.y; d0 = dv.x; d1 = dv.y;
  }
  if ((unsigned)d0 < (unsigned)N_NODES && (unsigned)s0 < (unsigned)N_NODES) {
    int r = atomicAdd(&g_deg[d0], 1);
    if (r < CAP) g_adj[d0 * CAP + r] = s0;
  }
  if ((unsigned)d1 < (unsigned)N_NODES && (unsigned)s1 < (unsigned)N_NODES) {
    int r = atomicAdd(&g_deg[d1], 1);
    if (r < CAP) g_adj[d1 * CAP + r] = s1;
  }
  // dropout mask: thread t -> elements t*8 .. t*8+7 (one byte of g_mask)
  unsigned ibase = (unsigned)t * 8u;
  unsigned byte = 0;
  #pragma unroll
  for (int b = 0; b < 8; b++) {
    unsigned r = tf_bits(ibase + (unsigned)b);
    byte |= (r < TF_KEEP_THRESH ? 1u : 0u) << b;
  }
  ((unsigned char*)g_mask)[t] = (unsigned char)byte;
}

// ---------------- dinv (+ packed-pair table) ----------------
__global__ void k_dinv() {
  int i = blockIdx.x * 256 + threadIdx.x;
  if (i < N_NODES) {
    float d = rsqrtf((float)(g_deg[i] + 1));
    g_dinv[i] = d;
    u64 p; PACK2(p, d);
    g_dinvp[i] = p;
  }
}

// ---------------- GEMM1: hs1 = x @ W1 (UNSCALED) -> fp32 (fully independent) ----------------
__global__ void __launch_bounds__(256) k_gemm1(const float* __restrict__ x,
                                               const float* __restrict__ W) {
  __shared__ float ws[128 * 64];   // 32 KB
  __shared__ float xs[32 * 128];   // 16 KB
  int tid = threadIdx.x;
  int n0 = blockIdx.x * 32;
  for (int t = tid; t < 128 * 64 / 4; t += 256)
    *(float4*)&ws[t * 4] = *(const float4*)&W[t * 4];
  for (int t = tid; t < 32 * 32; t += 256) {
    int r = t >> 5, kq = t & 31;
    *(float4*)&xs[r * 128 + kq * 4] = *(const float4*)&x[(size_t)(n0 + r) * 128 + kq * 4];
  }
  __syncthreads();
  int tx = tid & 15, ty = tid >> 4;
  u64 acc[2][2] = {};
  #pragma unroll 4
  for (int k4 = 0; k4 < 32; k4++) {
    float4 a0 = *(float4*)&xs[(ty * 2 + 0) * 128 + k4 * 4];
    float4 a1 = *(float4*)&xs[(ty * 2 + 1) * 128 + k4 * 4];
    #pragma unroll
    for (int kk = 0; kk < 4; kk++) {
      ulonglong2 bv = *(const ulonglong2*)&ws[(k4 * 4 + kk) * 64 + tx * 4];
      float v0 = ((const float*)&a0)[kk];
      float v1 = ((const float*)&a1)[kk];
      u64 vv0, vv1;
      PACK2(vv0, v0); PACK2(vv1, v1);
      FMA2(acc[0][0], vv0, bv.x); FMA2(acc[0][1], vv0, bv.y);
      FMA2(acc[1][0], vv1, bv.x); FMA2(acc[1][1], vv1, bv.y);
    }
  }
  #pragma unroll
  for (int i = 0; i < 2; i++) {
    int n = n0 + ty * 2 + i;
    float o0, o1, o2, o3;
    UNPACK2(o0, o1, acc[i][0]);
    UNPACK2(o2, o3, acc[i][1]);
    *(float4*)&g_hs1[(size_t)n * 64 + tx * 4] = make_float4(o0, o1, o2, o3);
  }
}

// ---------------- FUSED agg1 + GEMM2 (fp32 packed gather: LDG.64 + FMA2 per edge) ----------------
__global__ void __launch_bounds__(256) k_agg1_gemm2(const float* __restrict__ b1,
                                                    const float* __restrict__ W2) {
  __shared__ float h1s[64 * 64];   // 16 KB
  __shared__ float ws[64 * 32];    // 8 KB
  int tid = threadIdx.x;
  int lane = tid & 31, wid = tid >> 5;
  int nbase = blockIdx.x * 64;

  for (int t = tid; t < 64 * 32 / 4; t += 256)
    *(float4*)&ws[t * 4] = *(const float4*)&W2[t * 4];

  const u64* hs = (const u64*)g_hs1;   // 32 u64 (float-pairs) per row
  float2 bia = ((const float2*)b1)[lane];
  #pragma unroll 1
  for (int q = 0; q < 8; q++) {
    int node = nbase + wid * 8 + q;
    if (node >= N_NODES) break;
    int cnt = g_deg[node];
    cnt = cnt < CAP ? cnt : CAP;
    int base = node * CAP;
    float dd = g_dinv[node];
    u64 ddp = g_dinvp[node];
    u64 acc = 0;
    FMA2(acc, hs[(size_t)node * 32 + lane], ddp);   // self term: h_d * dinv_d
    int j = 0;
    for (; j + 8 <= cnt; j += 8) {
      int4 a = *(const int4*)&g_adj[base + j];
      int4 b = *(const int4*)&g_adj[base + j + 4];
      u64 p0 = g_dinvp[a.x], p1 = g_dinvp[a.y], p2 = g_dinvp[a.z], p3 = g_dinvp[a.w];
      u64 q0 = g_dinvp[b.x], q1 = g_dinvp[b.y], q2 = g_dinvp[b.z], q3 = g_dinvp[b.w];
      u64 v0 = hs[(size_t)a.x * 32 + lane];
      u64 v1 = hs[(size_t)a.y * 32 + lane];
      u64 v2 = hs[(size_t)a.z * 32 + lane];
      u64 v3 = hs[(size_t)a.w * 32 + lane];
      u64 v4 = hs[(size_t)b.x * 32 + lane];
      u64 v5 = hs[(size_t)b.y * 32 + lane];
      u64 v6 = hs[(size_t)b.z * 32 + lane];
      u64 v7 = hs[(size_t)b.w * 32 + lane];
      FMA2(acc, v0, p0); FMA2(acc, v1, p1); FMA2(acc, v2, p2); FMA2(acc, v3, p3);
      FMA2(acc, v4, q0); FMA2(acc, v5, q1); FMA2(acc, v6, q2); FMA2(acc, v7, q3);
    }
    if (j + 4 <= cnt) {
      int4 a = *(const int4*)&g_adj[base + j];
      u64 p0 = g_dinvp[a.x], p1 = g_dinvp[a.y], p2 = g_dinvp[a.z], p3 = g_dinvp[a.w];
      u64 v0 = hs[(size_t)a.x * 32 + lane];
      u64 v1 = hs[(size_t)a.y * 32 + lane];
      u64 v2 = hs[(size_t)a.z * 32 + lane];
      u64 v3 = hs[(size_t)a.w * 32 + lane];
      FMA2(acc, v0, p0); FMA2(acc, v1, p1); FMA2(acc, v2, p2); FMA2(acc, v3, p3);
      j += 4;
    }
    for (; j < cnt; j++) {
      int s = g_adj[base + j];
      FMA2(acc, hs[(size_t)s * 32 + lane], g_dinvp[s]);
    }
    float a0, a1;
    UNPACK2(a0, a1, acc);
    float o0 = fmaxf(a0 * dd + bia.x, 0.0f);
    float o1 = fmaxf(a1 * dd + bia.y, 0.0f);
    // dropout via precomputed mask: bits 2*lane, 2*lane+1 of g_mask[node]
    unsigned two = (unsigned)(g_mask[node] >> (2 * lane)) & 3u;
    float2 ov;
    ov.x = (two & 1u) ? o0 * INV_KEEP : 0.0f;
    ov.y = (two & 2u) ? o1 * INV_KEEP : 0.0f;
    *(float2*)&h1s[(wid * 8 + q) * 64 + 2 * lane] = ov;
  }
  __syncthreads();

  // Phase B: 64x64 @ 64x32 tile from smem -> hs2 (fp32, scaled by dinv[row])
  int tx = tid & 7, ty = tid >> 3;
  u64 acc[2][2] = {};
  #pragma unroll 4
  for (int k4 = 0; k4 < 16; k4++) {
    float4 a0 = *(float4*)&h1s[(ty * 2 + 0) * 64 + k4 * 4];
    float4 a1 = *(float4*)&h1s[(ty * 2 + 1) * 64 + k4 * 4];
    #pragma unroll
    for (int kk = 0; kk < 4; kk++) {
      ulonglong2 bv = *(const ulonglong2*)&ws[(k4 * 4 + kk) * 32 + tx * 4];
      float v0 = ((const float*)&a0)[kk];
      float v1 = ((const float*)&a1)[kk];
      u64 vv0, vv1;
      PACK2(vv0, v0); PACK2(vv1, v1);
      FMA2(acc[0][0], vv0, bv.x); FMA2(acc[0][1], vv0, bv.y);
      FMA2(acc[1][0], vv1, bv.x); FMA2(acc[1][1], vv1, bv.y);
    }
  }
  #pragma unroll
  for (int i = 0; i < 2; i++) {
    int n = nbase + ty * 2 + i;
    if (n < N_NODES) {
      float dv = g_dinv[n];
      float o0, o1, o2, o3;
      UNPACK2(o0, o1, acc[i][0]);
      UNPACK2(o2, o3, acc[i][1]);
      *(float4*)&g_hs2[(size_t)n * 32 + tx * 4] =
          make_float4(o0 * dv, o1 * dv, o2 * dv, o3 * dv);
    }
  }
}

// ---------------- agg2: split-warp packed gather (LDG.64 + ADD2); resets g_deg ----------------
__global__ void __launch_bounds__(256) k_agg2(const float* __restrict__ b2,
                                              float* __restrict__ out) {
  int node = blockIdx.x * 8 + (threadIdx.x >> 5);
  int lane = threadIdx.x & 31;
  int h = lane >> 4, l = lane & 15;
  const u64* hs = (const u64*)g_hs2;   // 16 u64 per row
  int cnt = g_deg[node];
  cnt = cnt < CAP ? cnt : CAP;
  int base = node * CAP;
  u64 acc = 0;
  int j = 0;
  for (; j + 16 <= cnt; j += 16) {
    int4 a = *(const int4*)&g_adj[base + j];
    int4 b = *(const int4*)&g_adj[base + j + 4];
    int4 c = *(const int4*)&g_adj[base + j + 8];
    int4 d = *(const int4*)&g_adj[base + j + 12];
    int s0 = h ? a.y : a.x, s1 = h ? a.w : a.z;
    int s2 = h ? b.y : b.x, s3 = h ? b.w : b.z;
    int s4 = h ? c.y : c.x, s5 = h ? c.w : c.z;
    int s6 = h ? d.y : d.x, s7 = h ? d.w : d.z;
    u64 v0 = hs[(size_t)s0 * 16 + l];
    u64 v1 = hs[(size_t)s1 * 16 + l];
    u64 v2 = hs[(size_t)s2 * 16 + l];
    u64 v3 = hs[(size_t)s3 * 16 + l];
    u64 v4 = hs[(size_t)s4 * 16 + l];
    u64 v5 = hs[(size_t)s5 * 16 + l];
    u64 v6 = hs[(size_t)s6 * 16 + l];
    u64 v7 = hs[(size_t)s7 * 16 + l];
    ADD2(acc, acc, v0); ADD2(acc, acc, v1); ADD2(acc, acc, v2); ADD2(acc, acc, v3);
    ADD2(acc, acc, v4); ADD2(acc, acc, v5); ADD2(acc, acc, v6); ADD2(acc, acc, v7);
  }
  for (; j + 4 <= cnt; j += 4) {
    int4 a = *(const int4*)&g_adj[base + j];
    int s0 = h ? a.y : a.x, s1 = h ? a.w : a.z;
    u64 v0 = hs[(size_t)s0 * 16 + l];
    u64 v1 = hs[(size_t)s1 * 16 + l];
    ADD2(acc, acc, v0); ADD2(acc, acc, v1);
  }
  for (; j < cnt; j += 2) {
    int idx = j + h;
    if (idx < cnt) {
      u64 v = hs[(size_t)g_adj[base + idx] * 16 + l];
      ADD2(acc, acc, v);
    }
  }
  // combine the two parity halves, add self
  u64 other = __shfl_xor_sync(0xffffffffu, acc, 16);
  ADD2(acc, acc, other);
  ADD2(acc, acc, hs[(size_t)node * 16 + l]);
  float a0, a1;
  UNPACK2(a0, a1, acc);
  float dv = g_dinv[node];
  float2 bb = ((const float2*)b2)[l];
  float2 o;
  o.x = a0 * dv + bb.x;
  o.y = a1 * dv + bb.y;
  if (h == 0)
    ((float2*)out)[(size_t)node * 16 + l] = o;
  // reset persistent state for the next replay (after all reads of deg[node])
  if (lane == 0) g_deg[node] = 0;
}

// ---------------- launch: [gemm1 || degfill+mask -> dinv] -> agg1_gemm2 -> agg2 ----------------
extern "C" void kernel_launch(void* const* d_in, const int* in_sizes, int n_in,
                              void* d_out, int out_size) {
  const float* x  = (const float*)d_in[0];
  const void*  ei = (const void*) d_in[1];
  const float* W1 = (const float*)d_in[2];
  const float* b1 = (const float*)d_in[3];
  const float* W2 = (const float*)d_in[4];
  const float* b2 = (const float*)d_in[5];
  float* out = (float*)d_out;

  static cudaStream_t s2 = nullptr;
  static cudaEvent_t ev_fork = nullptr, ev_g1 = nullptr;
  if (s2 == nullptr) {
    cudaStreamCreateWithFlags(&s2, cudaStreamNonBlocking);
    cudaEventCreateWithFlags(&ev_fork, cudaEventDisableTiming);
    cudaEventCreateWithFlags(&ev_g1, cudaEventDisableTiming);
  }

  const int NODE_BLKS  = (N_NODES + 255) / 256;  // 391
  const int EDGE2_BLKS = N_EDGES / 512;          // 3125

  // fork: gemm1 (fully independent) on side stream
  cudaEventRecord(ev_fork, 0);
  cudaStreamWaitEvent(s2, ev_fork, 0);
  k_gemm1<<<GEMM1_BLKS, 256, 0, s2>>>(x, W1);
  cudaEventRecord(ev_g1, s2);

  // main stream: single-pass CSR build + dropout mask + dinv
  k_degfill<<<EDGE2_BLKS, 256>>>(ei);
  k_dinv   <<<NODE_BLKS, 256>>>();

  cudaStreamWaitEvent(0, ev_g1, 0);
  k_agg1_gemm2<<<FB_BLKS, 256>>>(b1, W2);
  k_agg2      <<<N_NODES / 8, 256>>>(b2, out);
}

// round 13
// speedup vs baseline: 1.0419x; 1.0419x over previous
#include <cuda_runtime.h>
#include <cuda_fp16.h>
#include <stdint.h>

#define N_NODES 100000
#define N_EDGES 1600000
#define CAP 64                   // padded adjacency capacity (max degree << 64 here)
#define GEMM1_BLKS 3125          // 32 rows per block
#define FB_BLKS 1563             // fused agg1+gemm2: 64 nodes per block

typedef unsigned long long u64;

// ---------------- scratch (zero-initialized at load; agg2 re-zeros g_deg) ----------------
__device__ int    g_deg[N_NODES];            // edge count (self-loop NOT included)
__device__ float  g_dinv[N_NODES];
__device__ int    g_adj[N_NODES * CAP];      // padded adjacency
__device__ u64    g_mask[N_NODES];           // dropout keep-mask, bit k = element node*64+k
__device__ __half g_hs1[N_NODES * 64];       // x@W1 (UNSCALED), fp16 (row = 128B = 1 line)
__device__ __half g_hs2[N_NODES * 32];       // (h1@W2) * dinv[row], fp16 (row = 64B)

// ---------------- packed fp32x2 math ----------------
#define FMA2(d, a, b) \
  asm("fma.rn.f32x2 %0, %1, %2, %3;" : "=l"(d) : "l"(a), "l"(b), "l"(d))
#define PACK2(d, f) \
  asm("mov.b64 %0, {%1, %1};" : "=l"(d) : "f"(f))
#define UNPACK2(lo, hi, d) \
  asm("mov.b64 {%0, %1}, %2;" : "=f"(lo), "=f"(hi) : "l"(d))

// ---------------- per-block edge-dtype probe ----------------
__device__ __forceinline__ int probe_is64(const int* ei32, int tid, int* s_flag) {
  if (tid < 32) {
    int bad = (ei32[2 * tid + 1] != 0);
    unsigned m = __ballot_sync(0xffffffffu, bad);
    if (tid == 0) *s_flag = (m == 0);
  }
  __syncthreads();
  return *s_flag;
}

// ---------------- JAX threefry-2x32 (partitionable mode) ----------------
__device__ __forceinline__ unsigned tf_bits(unsigned i) {
  const unsigned ks0 = 0u;
  const unsigned ks1 = 42u;
  const unsigned ks2 = 0x1BD11BDAu ^ 0u ^ 42u;
  unsigned x0 = 0u + ks0;
  unsigned x1 = i  + ks1;
#define TF_R4(a,b,c,d) \
  x0 += x1; x1 = __funnelshift_l(x1, x1, (a)) ^ x0; \
  x0 += x1; x1 = __funnelshift_l(x1, x1, (b)) ^ x0; \
  x0 += x1; x1 = __funnelshift_l(x1, x1, (c)) ^ x0; \
  x0 += x1; x1 = __funnelshift_l(x1, x1, (d)) ^ x0;
  TF_R4(13,15,26, 6)  x0 += ks1; x1 += ks2 + 1u;
  TF_R4(17,29,16,24)  x0 += ks2; x1 += ks0 + 2u;
  TF_R4(13,15,26, 6)  x0 += ks0; x1 += ks1 + 3u;
  TF_R4(17,29,16,24)  x0 += ks1; x1 += ks2 + 4u;
  TF_R4(13,15,26, 6)  x0 += ks2; x1 += ks0 + 5u;
#undef TF_R4
  return x0 ^ x1;
}
#define TF_KEEP_THRESH 0xCCCCCE00u
#define INV_KEEP 1.25f

// ---------------- CSR build + dropout-mask generation ----------------
__global__ void k_degfill(const void* __restrict__ ei) {
  __shared__ int s_flag;
  int tid = threadIdx.x;
  int is64 = probe_is64((const int*)ei, tid, &s_flag);
  int t = blockIdx.x * 256 + tid;          // 0 .. 799999
  int e = t * 2;
  int s0, s1, d0, d1;
  if (is64) {
    longlong2 sv = *(const longlong2*)((const long long*)ei + e);
    longlong2 dv = *(const longlong2*)((const long long*)ei + N_EDGES + e);
    s0 = (int)sv.x; s1 = (int)sv.y; d0 = (int)dv.x; d1 = (int)dv.y;
  } else {
    int2 sv = *(const int2*)((const int*)ei + e);
    int2 dv = *(const int2*)((const int*)ei + N_EDGES + e);
    s0 = sv.x; s1 = sv.y; d0 = dv.x; d1 = dv.y;
  }
  if ((unsigned)d0 < (unsigned)N_NODES && (unsigned)s0 < (unsigned)N_NODES) {
    int r = atomicAdd(&g_deg[d0], 1);
    if (r < CAP) g_adj[d0 * CAP + r] = s0;
  }
  if ((unsigned)d1 < (unsigned)N_NODES && (unsigned)s1 < (unsigned)N_NODES) {
    int r = atomicAdd(&g_deg[d1], 1);
    if (r < CAP) g_adj[d1 * CAP + r] = s1;
  }
  // dropout mask: thread t -> elements t*8 .. t*8+7 (one byte of g_mask)
  unsigned ibase = (unsigned)t * 8u;
  unsigned byte = 0;
  #pragma unroll
  for (int b = 0; b < 8; b++) {
    unsigned r = tf_bits(ibase + (unsigned)b);
    byte |= (r < TF_KEEP_THRESH ? 1u : 0u) << b;
  }
  ((unsigned char*)g_mask)[t] = (unsigned char)byte;
}

// ---------------- dinv ----------------
__global__ void k_dinv() {
  int i = blockIdx.x * 256 + threadIdx.x;
  if (i < N_NODES) g_dinv[i] = rsqrtf((float)(g_deg[i] + 1));
}

// ---------------- GEMM1: hs1 = x @ W1 (UNSCALED) -> fp16 (fully independent) ----------------
__global__ void __launch_bounds__(256) k_gemm1(const float* __restrict__ x,
                                               const float* __restrict__ W) {
  __shared__ float ws[128 * 64];   // 32 KB
  __shared__ float xs[32 * 128];   // 16 KB
  int tid = threadIdx.x;
  int n0 = blockIdx.x * 32;
  for (int t = tid; t < 128 * 64 / 4; t += 256)
    *(float4*)&ws[t * 4] = *(const float4*)&W[t * 4];
  for (int t = tid; t < 32 * 32; t += 256) {
    int r = t >> 5, kq = t & 31;
    *(float4*)&xs[r * 128 + kq * 4] = *(const float4*)&x[(size_t)(n0 + r) * 128 + kq * 4];
  }
  __syncthreads();
  int tx = tid & 15, ty = tid >> 4;
  u64 acc[2][2] = {};
  #pragma unroll 4
  for (int k4 = 0; k4 < 32; k4++) {
    float4 a0 = *(float4*)&xs[(ty * 2 + 0) * 128 + k4 * 4];
    float4 a1 = *(float4*)&xs[(ty * 2 + 1) * 128 + k4 * 4];
    #pragma unroll
    for (int kk = 0; kk < 4; kk++) {
      ulonglong2 bv = *(const ulonglong2*)&ws[(k4 * 4 + kk) * 64 + tx * 4];
      float v0 = ((const float*)&a0)[kk];
      float v1 = ((const float*)&a1)[kk];
      u64 vv0, vv1;
      PACK2(vv0, v0); PACK2(vv1, v1);
      FMA2(acc[0][0], vv0, bv.x); FMA2(acc[0][1], vv0, bv.y);
      FMA2(acc[1][0], vv1, bv.x); FMA2(acc[1][1], vv1, bv.y);
    }
  }
  #pragma unroll
  for (int i = 0; i < 2; i++) {
    int n = n0 + ty * 2 + i;
    float o0, o1, o2, o3;
    UNPACK2(o0, o1, acc[i][0]);
    UNPACK2(o2, o3, acc[i][1]);
    __half2* hp = (__half2*)&g_hs1[(size_t)n * 64 + tx * 4];
    hp[0] = __float22half2_rn(make_float2(o0, o1));
    hp[1] = __float22half2_rn(make_float2(o2, o3));
  }
}

// ---------------- FUSED agg1 + GEMM2 (fp16 gather = 1 line/edge; mask dropout) ----------------
__global__ void __launch_bounds__(256) k_agg1_gemm2(const float* __restrict__ b1,
                                                    const float* __restrict__ W2) {
  __shared__ float h1s[64 * 64];   // 16 KB
  __shared__ float ws[64 * 32];    // 8 KB
  int tid = threadIdx.x;
  int lane = tid & 31, wid = tid >> 5;
  int nbase = blockIdx.x * 64;

  for (int t = tid; t < 64 * 32 / 4; t += 256)
    *(float4*)&ws[t * 4] = *(const float4*)&W2[t * 4];

  const __half2* hs = (const __half2*)g_hs1;   // 32 half2 per row (unscaled)
  float2 bia = ((const float2*)b1)[lane];
  #pragma unroll 1
  for (int q = 0; q < 8; q++) {
    int node = nbase + wid * 8 + q;
    if (node >= N_NODES) break;
    int cnt = g_deg[node];
    cnt = cnt < CAP ? cnt : CAP;
    int base = node * CAP;
    float dd = g_dinv[node];
    float2 sv = __half22float2(hs[(size_t)node * 32 + lane]);
    float2 acc;
    acc.x = sv.x * dd; acc.y = sv.y * dd;      // self term: h_d * dinv_d
    int j = 0;
    for (; j + 8 <= cnt; j += 8) {
      int4 a = *(const int4*)&g_adj[base + j];
      int4 b = *(const int4*)&g_adj[base + j + 4];
      float da0 = g_dinv[a.x], da1 = g_dinv[a.y], da2 = g_dinv[a.z], da3 = g_dinv[a.w];
      float db0 = g_dinv[b.x], db1 = g_dinv[b.y], db2 = g_dinv[b.z], db3 = g_dinv[b.w];
      float2 v0 = __half22float2(hs[(size_t)a.x * 32 + lane]);
      float2 v1 = __half22float2(hs[(size_t)a.y * 32 + lane]);
      float2 v2 = __half22float2(hs[(size_t)a.z * 32 + lane]);
      float2 v3 = __half22float2(hs[(size_t)a.w * 32 + lane]);
      float2 v4 = __half22float2(hs[(size_t)b.x * 32 + lane]);
      float2 v5 = __half22float2(hs[(size_t)b.y * 32 + lane]);
      float2 v6 = __half22float2(hs[(size_t)b.z * 32 + lane]);
      float2 v7 = __half22float2(hs[(size_t)b.w * 32 + lane]);
      acc.x = fmaf(v0.x, da0, acc.x); acc.y = fmaf(v0.y, da0, acc.y);
      acc.x = fmaf(v1.x, da1, acc.x); acc.y = fmaf(v1.y, da1, acc.y);
      acc.x = fmaf(v2.x, da2, acc.x); acc.y = fmaf(v2.y, da2, acc.y);
      acc.x = fmaf(v3.x, da3, acc.x); acc.y = fmaf(v3.y, da3, acc.y);
      acc.x = fmaf(v4.x, db0, acc.x); acc.y = fmaf(v4.y, db0, acc.y);
      acc.x = fmaf(v5.x, db1, acc.x); acc.y = fmaf(v5.y, db1, acc.y);
      acc.x = fmaf(v6.x, db2, acc.x); acc.y = fmaf(v6.y, db2, acc.y);
      acc.x = fmaf(v7.x, db3, acc.x); acc.y = fmaf(v7.y, db3, acc.y);
    }
    if (j + 4 <= cnt) {
      int4 a = *(const int4*)&g_adj[base + j];
      float da0 = g_dinv[a.x], da1 = g_dinv[a.y], da2 = g_dinv[a.z], da3 = g_dinv[a.w];
      float2 v0 = __half22float2(hs[(size_t)a.x * 32 + lane]);
      float2 v1 = __half22float2(hs[(size_t)a.y * 32 + lane]);
      float2 v2 = __half22float2(hs[(size_t)a.z * 32 + lane]);
      float2 v3 = __half22float2(hs[(size_t)a.w * 32 + lane]);
      acc.x = fmaf(v0.x, da0, acc.x); acc.y = fmaf(v0.y, da0, acc.y);
      acc.x = fmaf(v1.x, da1, acc.x); acc.y = fmaf(v1.y, da1, acc.y);
      acc.x = fmaf(v2.x, da2, acc.x); acc.y = fmaf(v2.y, da2, acc.y);
      acc.x = fmaf(v3.x, da3, acc.x); acc.y = fmaf(v3.y, da3, acc.y);
      j += 4;
    }
    for (; j < cnt; j++) {
      int s = g_adj[base + j];
      float ds = g_dinv[s];
      float2 v = __half22float2(hs[(size_t)s * 32 + lane]);
      acc.x = fmaf(v.x, ds, acc.x); acc.y = fmaf(v.y, ds, acc.y);
    }
    float o0 = fmaxf(acc.x * dd + bia.x, 0.0f);
    float o1 = fmaxf(acc.y * dd + bia.y, 0.0f);
    unsigned two = (unsigned)(g_mask[node] >> (2 * lane)) & 3u;
    float2 ov;
    ov.x = (two & 1u) ? o0 * INV_KEEP : 0.0f;
    ov.y = (two & 2u) ? o1 * INV_KEEP : 0.0f;
    *(float2*)&h1s[(wid * 8 + q) * 64 + 2 * lane] = ov;
  }
  __syncthreads();

  // Phase B: 64x64 @ 64x32 tile from smem -> hs2 (fp16, scaled by dinv[row])
  int tx = tid & 7, ty = tid >> 3;
  u64 acc[2][2] = {};
  #pragma unroll 4
  for (int k4 = 0; k4 < 16; k4++) {
    float4 a0 = *(float4*)&h1s[(ty * 2 + 0) * 64 + k4 * 4];
    float4 a1 = *(float4*)&h1s[(ty * 2 + 1) * 64 + k4 * 4];
    #pragma unroll
    for (int kk = 0; kk < 4; kk++) {
      ulonglong2 bv = *(const ulonglong2*)&ws[(k4 * 4 + kk) * 32 + tx * 4];
      float v0 = ((const float*)&a0)[kk];
      float v1 = ((const float*)&a1)[kk];
      u64 vv0, vv1;
      PACK2(vv0, v0); PACK2(vv1, v1);
      FMA2(acc[0][0], vv0, bv.x); FMA2(acc[0][1], vv0, bv.y);
      FMA2(acc[1][0], vv1, bv.x); FMA2(acc[1][1], vv1, bv.y);
    }
  }
  #pragma unroll
  for (int i = 0; i < 2; i++) {
    int n = nbase + ty * 2 + i;
    if (n < N_NODES) {
      float dv = g_dinv[n];
      float o0, o1, o2, o3;
      UNPACK2(o0, o1, acc[i][0]);
      UNPACK2(o2, o3, acc[i][1]);
      __half2* hp = (__half2*)&g_hs2[(size_t)n * 32 + tx * 4];
      hp[0] = __float22half2_rn(make_float2(o0 * dv, o1 * dv));
      hp[1] = __float22half2_rn(make_float2(o2 * dv, o3 * dv));
    }
  }
}

// ---------------- agg2: 8-lane groups, 4 edges per warp-load; resets g_deg ----------------
__global__ void __launch_bounds__(256) k_agg2(const float* __restrict__ b2,
                                              float* __restrict__ out) {
  int node = blockIdx.x * 8 + (threadIdx.x >> 5);
  int lane = threadIdx.x & 31;
  int grp = lane >> 3, l = lane & 7;           // 4 groups x 8 lanes
  const u64* hs = (const u64*)g_hs2;           // 8 u64 (4 halves) per 64B row
  int cnt = g_deg[node];
  cnt = cnt < CAP ? cnt : CAP;
  int base = node * CAP;
  float2 acc0 = make_float2(0.f, 0.f);         // cols 4l+0,4l+1
  float2 acc1 = make_float2(0.f, 0.f);         // cols 4l+2,4l+3
  int j = 0;
  for (; j + 8 <= cnt; j += 8) {
    int4 a = *(const int4*)&g_adj[base + j];
    int4 b = *(const int4*)&g_adj[base + j + 4];
    int sA = grp == 0 ? a.x : grp == 1 ? a.y : grp == 2 ? a.z : a.w;
    int sB = grp == 0 ? b.x : grp == 1 ? b.y : grp == 2 ? b.z : b.w;
    u64 vA = hs[(size_t)sA * 8 + l];
    u64 vB = hs[(size_t)sB * 8 + l];
    __half2 alo = *(__half2*)&vA, ahi = *((__half2*)&vA + 1);
    __half2 blo = *(__half2*)&vB, bhi = *((__half2*)&vB + 1);
    float2 fa0 = __half22float2(alo), fa1 = __half22float2(ahi);
    float2 fb0 = __half22float2(blo), fb1 = __half22float2(bhi);
    acc0.x += fa0.x + fb0.x; acc0.y += fa0.y + fb0.y;
    acc1.x += fa1.x + fb1.x; acc1.y += fa1.y + fb1.y;
  }
  if (j + 4 <= cnt) {
    int4 a = *(const int4*)&g_adj[base + j];
    int sA = grp == 0 ? a.x : grp == 1 ? a.y : grp == 2 ? a.z : a.w;
    u64 vA = hs[(size_t)sA * 8 + l];
    __half2 alo = *(__half2*)&vA, ahi = *((__half2*)&vA + 1);
    float2 fa0 = __half22float2(alo), fa1 = __half22float2(ahi);
    acc0.x += fa0.x; acc0.y += fa0.y;
    acc1.x += fa1.x; acc1.y += fa1.y;
    j += 4;
  }
  for (; j < cnt; j += 4) {
    int idx = j + grp;
    if (idx < cnt) {
      u64 v = hs[(size_t)g_adj[base + idx] * 8 + l];
      __half2 lo = *(__half2*)&v, hi = *((__half2*)&v + 1);
      float2 f0 = __half22float2(lo), f1 = __half22float2(hi);
      acc0.x += f0.x; acc0.y += f0.y;
      acc1.x += f1.x; acc1.y += f1.y;
    }
  }
  // combine the 4 groups (xor 8, then 16)
  #pragma unroll
  for (int o = 8; o <= 16; o <<= 1) {
    acc0.x += __shfl_xor_sync(0xffffffffu, acc0.x, o);
    acc0.y += __shfl_xor_sync(0xffffffffu, acc0.y, o);
    acc1.x += __shfl_xor_sync(0xffffffffu, acc1.x, o);
    acc1.y += __shfl_xor_sync(0xffffffffu, acc1.y, o);
  }
  // self + scale + bias; group 0's 8 lanes write the 32-col row (float4 each)
  if (grp == 0) {
    u64 v = hs[(size_t)node * 8 + l];
    __half2 lo = *(__half2*)&v, hi = *((__half2*)&v + 1);
    float2 s0 = __half22float2(lo), s1 = __half22float2(hi);
    float dv = g_dinv[node];
    float4 bb = ((const float4*)b2)[l];
    float4 o;
    o.x = (acc0.x + s0.x) * dv + bb.x;
    o.y = (acc0.y + s0.y) * dv + bb.y;
    o.z = (acc1.x + s1.x) * dv + bb.z;
    o.w = (acc1.y + s1.y) * dv + bb.w;
    ((float4*)out)[(size_t)node * 8 + l] = o;
  }
  // reset persistent state for the next replay (after all reads of deg[node])
  if (lane == 0) g_deg[node] = 0;
}

// ---------------- launch: [gemm1 || degfill+mask -> dinv] -> agg1_gemm2 -> agg2 ----------------
extern "C" void kernel_launch(void* const* d_in, const int* in_sizes, int n_in,
                              void* d_out, int out_size) {
  const float* x  = (const float*)d_in[0];
  const void*  ei = (const void*) d_in[1];
  const float* W1 = (const float*)d_in[2];
  const float* b1 = (const float*)d_in[3];
  const float* W2 = (const float*)d_in[4];
  const float* b2 = (const float*)d_in[5];
  float* out = (float*)d_out;

  static cudaStream_t s2 = nullptr;
  static cudaEvent_t ev_fork = nullptr, ev_g1 = nullptr;
  if (s2 == nullptr) {
    cudaStreamCreateWithFlags(&s2, cudaStreamNonBlocking);
    cudaEventCreateWithFlags(&ev_fork, cudaEventDisableTiming);
    cudaEventCreateWithFlags(&ev_g1, cudaEventDisableTiming);
  }

  const int NODE_BLKS  = (N_NODES + 255) / 256;  // 391
  const int EDGE2_BLKS = N_EDGES / 512;          // 3125

  // fork: gemm1 (fully independent) on side stream
  cudaEventRecord(ev_fork, 0);
  cudaStreamWaitEvent(s2, ev_fork, 0);
  k_gemm1<<<GEMM1_BLKS, 256, 0, s2>>>(x, W1);
  cudaEventRecord(ev_g1, s2);

  // main stream: single-pass CSR build + dropout mask + dinv
  k_degfill<<<EDGE2_BLKS, 256>>>(ei);
  k_dinv   <<<NODE_BLKS, 256>>>();

  cudaStreamWaitEvent(0, ev_g1, 0);
  k_agg1_gemm2<<<FB_BLKS, 256>>>(b1, W2);
  k_agg2      <<<N_NODES / 8, 256>>>(b2, out);
}

// round 14
// speedup vs baseline: 1.6969x; 1.6287x over previous
#include <cuda_runtime.h>
#include <cuda_fp16.h>
#include <stdint.h>

#define N_NODES 100000
#define N_EDGES 1600000
#define CAP 64                   // padded adjacency capacity (max degree << 64 here)
#define GEMM1_BLKS 3125          // 32 rows per block
#define FB_BLKS 1563             // fused agg1+gemm2: 64 nodes per block

typedef unsigned long long u64;

// ---------------- scratch (zero-initialized at load; agg2 re-zeros g_deg) ----------------
__device__ int    g_deg[N_NODES];            // edge count (self-loop NOT included)
__device__ float  g_dinv[N_NODES];
__device__ int    g_adj[N_NODES * CAP];      // padded adjacency (slots >= cnt stay 0)
__device__ u64    g_mask[N_NODES];           // dropout keep-mask, bit k = element node*64+k
__device__ __half g_hs1[N_NODES * 64];       // x@W1 (UNSCALED), fp16 (row = 128B = 1 line)
__device__ __half g_hs2[N_NODES * 32];       // (h1@W2) * dinv[row], fp16 (row = 64B)

// ---------------- packed fp32x2 math ----------------
#define FMA2(d, a, b) \
  asm("fma.rn.f32x2 %0, %1, %2, %3;" : "=l"(d) : "l"(a), "l"(b), "l"(d))
#define PACK2(d, f) \
  asm("mov.b64 %0, {%1, %1};" : "=l"(d) : "f"(f))
#define UNPACK2(lo, hi, d) \
  asm("mov.b64 {%0, %1}, %2;" : "=f"(lo), "=f"(hi) : "l"(d))

// ---------------- per-block edge-dtype probe ----------------
__device__ __forceinline__ int probe_is64(const int* ei32, int tid, int* s_flag) {
  if (tid < 32) {
    int bad = (ei32[2 * tid + 1] != 0);
    unsigned m = __ballot_sync(0xffffffffu, bad);
    if (tid == 0) *s_flag = (m == 0);
  }
  __syncthreads();
  return *s_flag;
}

// ---------------- JAX threefry-2x32 (partitionable mode) ----------------
__device__ __forceinline__ unsigned tf_bits(unsigned i) {
  const unsigned ks0 = 0u;
  const unsigned ks1 = 42u;
  const unsigned ks2 = 0x1BD11BDAu ^ 0u ^ 42u;
  unsigned x0 = 0u + ks0;
  unsigned x1 = i  + ks1;
#define TF_R4(a,b,c,d) \
  x0 += x1; x1 = __funnelshift_l(x1, x1, (a)) ^ x0; \
  x0 += x1; x1 = __funnelshift_l(x1, x1, (b)) ^ x0; \
  x0 += x1; x1 = __funnelshift_l(x1, x1, (c)) ^ x0; \
  x0 += x1; x1 = __funnelshift_l(x1, x1, (d)) ^ x0;
  TF_R4(13,15,26, 6)  x0 += ks1; x1 += ks2 + 1u;
  TF_R4(17,29,16,24)  x0 += ks2; x1 += ks0 + 2u;
  TF_R4(13,15,26, 6)  x0 += ks0; x1 += ks1 + 3u;
  TF_R4(17,29,16,24)  x0 += ks1; x1 += ks2 + 4u;
  TF_R4(13,15,26, 6)  x0 += ks2; x1 += ks0 + 5u;
#undef TF_R4
  return x0 ^ x1;
}
#define TF_KEEP_THRESH 0xCCCCCE00u
#define INV_KEEP 1.25f

// ---------------- CSR build + dropout-mask generation ----------------
__global__ void k_degfill(const void* __restrict__ ei) {
  __shared__ int s_flag;
  int tid = threadIdx.x;
  int is64 = probe_is64((const int*)ei, tid, &s_flag);
  int t = blockIdx.x * 256 + tid;          // 0 .. 799999
  int e = t * 2;
  int s0, s1, d0, d1;
  if (is64) {
    longlong2 sv = *(const longlong2*)((const long long*)ei + e);
    longlong2 dv = *(const longlong2*)((const long long*)ei + N_EDGES + e);
    s0 = (int)sv.x; s1 = (int)sv.y; d0 = (int)dv.x; d1 = (int)dv.y;
  } else {
    int2 sv = *(const int2*)((const int*)ei + e);
    int2 dv = *(const int2*)((const int*)ei + N_EDGES + e);
    s0 = sv.x; s1 = sv.y; d0 = dv.x; d1 = dv.y;
  }
  if ((unsigned)d0 < (unsigned)N_NODES && (unsigned)s0 < (unsigned)N_NODES) {
    int r = atomicAdd(&g_deg[d0], 1);
    if (r < CAP) g_adj[d0 * CAP + r] = s0;
  }
  if ((unsigned)d1 < (unsigned)N_NODES && (unsigned)s1 < (unsigned)N_NODES) {
    int r = atomicAdd(&g_deg[d1], 1);
    if (r < CAP) g_adj[d1 * CAP + r] = s1;
  }
  // dropout mask: thread t -> elements t*8 .. t*8+7 (one byte of g_mask)
  unsigned ibase = (unsigned)t * 8u;
  unsigned byte = 0;
  #pragma unroll
  for (int b = 0; b < 8; b++) {
    unsigned r = tf_bits(ibase + (unsigned)b);
    byte |= (r < TF_KEEP_THRESH ? 1u : 0u) << b;
  }
  ((unsigned char*)g_mask)[t] = (unsigned char)byte;
}

// ---------------- dinv ----------------
__global__ void k_dinv() {
  int i = blockIdx.x * 256 + threadIdx.x;
  if (i < N_NODES) g_dinv[i] = rsqrtf((float)(g_deg[i] + 1));
}

// ---------------- GEMM1: hs1 = x @ W1 (UNSCALED) -> fp16 (fully independent) ----------------
__global__ void __launch_bounds__(256) k_gemm1(const float* __restrict__ x,
                                               const float* __restrict__ W) {
  __shared__ float ws[128 * 64];   // 32 KB
  __shared__ float xs[32 * 128];   // 16 KB
  int tid = threadIdx.x;
  int n0 = blockIdx.x * 32;
  for (int t = tid; t < 128 * 64 / 4; t += 256)
    *(float4*)&ws[t * 4] = *(const float4*)&W[t * 4];
  for (int t = tid; t < 32 * 32; t += 256) {
    int r = t >> 5, kq = t & 31;
    *(float4*)&xs[r * 128 + kq * 4] = *(const float4*)&x[(size_t)(n0 + r) * 128 + kq * 4];
  }
  __syncthreads();
  int tx = tid & 15, ty = tid >> 4;
  u64 acc[2][2] = {};
  #pragma unroll 4
  for (int k4 = 0; k4 < 32; k4++) {
    float4 a0 = *(float4*)&xs[(ty * 2 + 0) * 128 + k4 * 4];
    float4 a1 = *(float4*)&xs[(ty * 2 + 1) * 128 + k4 * 4];
    #pragma unroll
    for (int kk = 0; kk < 4; kk++) {
      ulonglong2 bv = *(const ulonglong2*)&ws[(k4 * 4 + kk) * 64 + tx * 4];
      float v0 = ((const float*)&a0)[kk];
      float v1 = ((const float*)&a1)[kk];
      u64 vv0, vv1;
      PACK2(vv0, v0); PACK2(vv1, v1);
      FMA2(acc[0][0], vv0, bv.x); FMA2(acc[0][1], vv0, bv.y);
      FMA2(acc[1][0], vv1, bv.x); FMA2(acc[1][1], vv1, bv.y);
    }
  }
  #pragma unroll
  for (int i = 0; i < 2; i++) {
    int n = n0 + ty * 2 + i;
    float o0, o1, o2, o3;
    UNPACK2(o0, o1, acc[i][0]);
    UNPACK2(o2, o3, acc[i][1]);
    __half2* hp = (__half2*)&g_hs1[(size_t)n * 64 + tx * 4];
    hp[0] = __float22half2_rn(make_float2(o0, o1));
    hp[1] = __float22half2_rn(make_float2(o2, o3));
  }
}

// ---------------- FUSED agg1 + GEMM2: batched-16 gather (one latency stage) ----------------
__global__ void __launch_bounds__(256) k_agg1_gemm2(const float* __restrict__ b1,
                                                    const float* __restrict__ W2) {
  __shared__ float h1s[64 * 64];   // 16 KB
  __shared__ float ws[64 * 32];    // 8 KB
  int tid = threadIdx.x;
  int lane = tid & 31, wid = tid >> 5;
  int nbase = blockIdx.x * 64;

  for (int t = tid; t < 64 * 32 / 4; t += 256)
    *(float4*)&ws[t * 4] = *(const float4*)&W2[t * 4];

  const __half2* hs = (const __half2*)g_hs1;   // 32 half2 per row (unscaled)
  float2 bia = ((const float2*)b1)[lane];
  #pragma unroll 1
  for (int q = 0; q < 8; q++) {
    int node = nbase + wid * 8 + q;
    if (node >= N_NODES) break;
    int cnt = g_deg[node];
    cnt = cnt < CAP ? cnt : CAP;
    int base = node * CAP;
    float dd = g_dinv[node];
    float2 sv = __half22float2(hs[(size_t)node * 32 + lane]);
    float2 acc;
    acc.x = sv.x * dd; acc.y = sv.y * dd;      // self term: h_d * dinv_d
    // --- batched first 16 edges: all adj loads up front, all gathers unconditional ---
    // Padded row: slots >= cnt are 0 (zero-init, deterministic refill) -> safe indices.
    int4 A = *(const int4*)&g_adj[base];
    int4 B = *(const int4*)&g_adj[base + 4];
    int4 C = *(const int4*)&g_adj[base + 8];
    int4 D = *(const int4*)&g_adj[base + 12];
    int ss[16];
    ss[0] = A.x; ss[1] = A.y; ss[2]  = A.z; ss[3]  = A.w;
    ss[4] = B.x; ss[5] = B.y; ss[6]  = B.z; ss[7]  = B.w;
    ss[8] = C.x; ss[9] = C.y; ss[10] = C.z; ss[11] = C.w;
    ss[12] = D.x; ss[13] = D.y; ss[14] = D.z; ss[15] = D.w;
    #pragma unroll
    for (int k = 0; k < 16; k++) {
      int s = ss[k];
      float w = (k < cnt) ? g_dinv[s] : 0.0f;
      float2 v = __half22float2(hs[(size_t)s * 32 + lane]);
      acc.x = fmaf(v.x, w, acc.x);
      acc.y = fmaf(v.y, w, acc.y);
    }
    // --- tail: edges 16..cnt (Poisson-16 tail, ~10% of edge mass) ---
    int j = 16;
    for (; j + 4 <= cnt; j += 4) {
      int4 a = *(const int4*)&g_adj[base + j];
      float da0 = g_dinv[a.x], da1 = g_dinv[a.y], da2 = g_dinv[a.z], da3 = g_dinv[a.w];
      float2 v0 = __half22float2(hs[(size_t)a.x * 32 + lane]);
      float2 v1 = __half22float2(hs[(size_t)a.y * 32 + lane]);
      float2 v2 = __half22float2(hs[(size_t)a.z * 32 + lane]);
      float2 v3 = __half22float2(hs[(size_t)a.w * 32 + lane]);
      acc.x = fmaf(v0.x, da0, acc.x); acc.y = fmaf(v0.y, da0, acc.y);
      acc.x = fmaf(v1.x, da1, acc.x); acc.y = fmaf(v1.y, da1, acc.y);
      acc.x = fmaf(v2.x, da2, acc.x); acc.y = fmaf(v2.y, da2, acc.y);
      acc.x = fmaf(v3.x, da3, acc.x); acc.y = fmaf(v3.y, da3, acc.y);
    }
    for (; j < cnt; j++) {
      int s = g_adj[base + j];
      float ds = g_dinv[s];
      float2 v = __half22float2(hs[(size_t)s * 32 + lane]);
      acc.x = fmaf(v.x, ds, acc.x); acc.y = fmaf(v.y, ds, acc.y);
    }
    float o0 = fmaxf(acc.x * dd + bia.x, 0.0f);
    float o1 = fmaxf(acc.y * dd + bia.y, 0.0f);
    unsigned two = (unsigned)(g_mask[node] >> (2 * lane)) & 3u;
    float2 ov;
    ov.x = (two & 1u) ? o0 * INV_KEEP : 0.0f;
    ov.y = (two & 2u) ? o1 * INV_KEEP : 0.0f;
    *(float2*)&h1s[(wid * 8 + q) * 64 + 2 * lane] = ov;
  }
  __syncthreads();

  // Phase B: 64x64 @ 64x32 tile from smem -> hs2 (fp16, scaled by dinv[row])
  int tx = tid & 7, ty = tid >> 3;
  u64 acc[2][2] = {};
  #pragma unroll 4
  for (int k4 = 0; k4 < 16; k4++) {
    float4 a0 = *(float4*)&h1s[(ty * 2 + 0) * 64 + k4 * 4];
    float4 a1 = *(float4*)&h1s[(ty * 2 + 1) * 64 + k4 * 4];
    #pragma unroll
    for (int kk = 0; kk < 4; kk++) {
      ulonglong2 bv = *(const ulonglong2*)&ws[(k4 * 4 + kk) * 32 + tx * 4];
      float v0 = ((const float*)&a0)[kk];
      float v1 = ((const float*)&a1)[kk];
      u64 vv0, vv1;
      PACK2(vv0, v0); PACK2(vv1, v1);
      FMA2(acc[0][0], vv0, bv.x); FMA2(acc[0][1], vv0, bv.y);
      FMA2(acc[1][0], vv1, bv.x); FMA2(acc[1][1], vv1, bv.y);
    }
  }
  #pragma unroll
  for (int i = 0; i < 2; i++) {
    int n = nbase + ty * 2 + i;
    if (n < N_NODES) {
      float dv = g_dinv[n];
      float o0, o1, o2, o3;
      UNPACK2(o0, o1, acc[i][0]);
      UNPACK2(o2, o3, acc[i][1]);
      __half2* hp = (__half2*)&g_hs2[(size_t)n * 32 + tx * 4];
      hp[0] = __float22half2_rn(make_float2(o0 * dv, o1 * dv));
      hp[1] = __float22half2_rn(make_float2(o2 * dv, o3 * dv));
    }
  }
}

// ---------------- agg2 (R11 split-warp form): 2 edges per load; resets g_deg ----------------
__global__ void __launch_bounds__(256) k_agg2(const float* __restrict__ b2,
                                              float* __restrict__ out) {
  int node = blockIdx.x * 8 + (threadIdx.x >> 5);
  int lane = threadIdx.x & 31;
  int g = lane >> 4, l = lane & 15;
  const __half2* hs = (const __half2*)g_hs2;   // 16 half2 per row
  int cnt = g_deg[node];
  cnt = cnt < CAP ? cnt : CAP;
  int base = node * CAP;
  float2 acc = make_float2(0.0f, 0.0f);
  int j = 0;
  for (; j + 16 <= cnt; j += 16) {
    int4 a = *(const int4*)&g_adj[base + j];
    int4 b = *(const int4*)&g_adj[base + j + 4];
    int4 c = *(const int4*)&g_adj[base + j + 8];
    int4 d = *(const int4*)&g_adj[base + j + 12];
    int s0 = g ? a.y : a.x, s1 = g ? a.w : a.z;
    int s2 = g ? b.y : b.x, s3 = g ? b.w : b.z;
    int s4 = g ? c.y : c.x, s5 = g ? c.w : c.z;
    int s6 = g ? d.y : d.x, s7 = g ? d.w : d.z;
    float2 v0 = __half22float2(hs[(size_t)s0 * 16 + l]);
    float2 v1 = __half22float2(hs[(size_t)s1 * 16 + l]);
    float2 v2 = __half22float2(hs[(size_t)s2 * 16 + l]);
    float2 v3 = __half22float2(hs[(size_t)s3 * 16 + l]);
    float2 v4 = __half22float2(hs[(size_t)s4 * 16 + l]);
    float2 v5 = __half22float2(hs[(size_t)s5 * 16 + l]);
    float2 v6 = __half22float2(hs[(size_t)s6 * 16 + l]);
    float2 v7 = __half22float2(hs[(size_t)s7 * 16 + l]);
    acc.x += ((v0.x + v1.x) + (v2.x + v3.x)) + ((v4.x + v5.x) + (v6.x + v7.x));
    acc.y += ((v0.y + v1.y) + (v2.y + v3.y)) + ((v4.y + v5.y) + (v6.y + v7.y));
  }
  for (; j + 4 <= cnt; j += 4) {
    int4 a = *(const int4*)&g_adj[base + j];
    int s0 = g ? a.y : a.x, s1 = g ? a.w : a.z;
    float2 v0 = __half22float2(hs[(size_t)s0 * 16 + l]);
    float2 v1 = __half22float2(hs[(size_t)s1 * 16 + l]);
    acc.x += v0.x + v1.x;
    acc.y += v0.y + v1.y;
  }
  for (; j < cnt; j += 2) {
    int idx = j + g;
    if (idx < cnt) {
      float2 v = __half22float2(hs[(size_t)g_adj[base + idx] * 16 + l]);
      acc.x += v.x; acc.y += v.y;
    }
  }
  acc.x += __shfl_xor_sync(0xffffffffu, acc.x, 16);
  acc.y += __shfl_xor_sync(0xffffffffu, acc.y, 16);
  float2 sv = __half22float2(hs[(size_t)node * 16 + l]);
  float dv = g_dinv[node];
  float2 bb = ((const float2*)b2)[l];
  float2 o;
  o.x = (acc.x + sv.x) * dv + bb.x;
  o.y = (acc.y + sv.y) * dv + bb.y;
  if (g == 0)
    ((float2*)out)[(size_t)node * 16 + l] = o;
  // reset persistent state for the next replay (after all reads of deg[node])
  if (lane == 0) g_deg[node] = 0;
}

// ---------------- launch: [gemm1 || degfill+mask -> dinv] -> agg1_gemm2 -> agg2 ----------------
extern "C" void kernel_launch(void* const* d_in, const int* in_sizes, int n_in,
                              void* d_out, int out_size) {
  const float* x  = (const float*)d_in[0];
  const void*  ei = (const void*) d_in[1];
  const float* W1 = (const float*)d_in[2];
  const float* b1 = (const float*)d_in[3];
  const float* W2 = (const float*)d_in[4];
  const float* b2 = (const float*)d_in[5];
  float* out = (float*)d_out;

  static cudaStream_t s2 = nullptr;
  static cudaEvent_t ev_fork = nullptr, ev_g1 = nullptr;
  if (s2 == nullptr) {
    cudaStreamCreateWithFlags(&s2, cudaStreamNonBlocking);
    cudaEventCreateWithFlags(&ev_fork, cudaEventDisableTiming);
    cudaEventCreateWithFlags(&ev_g1, cudaEventDisableTiming);
  }

  const int NODE_BLKS  = (N_NODES + 255) / 256;  // 391
  const int EDGE2_BLKS = N_EDGES / 512;          // 3125

  // fork: gemm1 (fully independent) on side stream
  cudaEventRecord(ev_fork, 0);
  cudaStreamWaitEvent(s2, ev_fork, 0);
  k_gemm1<<<GEMM1_BLKS, 256, 0, s2>>>(x, W1);
  cudaEventRecord(ev_g1, s2);

  // main stream: single-pass CSR build + dropout mask + dinv
  k_degfill<<<EDGE2_BLKS, 256>>>(ei);
  k_dinv   <<<NODE_BLKS, 256>>>();

  cudaStreamWaitEvent(0, ev_g1, 0);
  k_agg1_gemm2<<<FB_BLKS, 256>>>(b1, W2);
  k_agg2      <<<N_NODES / 8, 256>>>(b2, out);
}